// round 3
// baseline (speedup 1.0000x reference)
#include <cuda_runtime.h>
#include <cstdint>

#define NN 50000
#define NE 625000
#define NTOT (NN + NE)

// ---------------- scratch (static device globals; no allocation) ----------------
__device__ float g_bufA[(size_t)NN * 128];   // 25.6 MB
__device__ float g_bufB[(size_t)NN * 128];   // 25.6 MB
__device__ int   g_deg[NN];
__device__ float g_dinv[NN];
__device__ int   g_rowptr[NN + 1];
__device__ int   g_cursor[NN];
__device__ int   g_srcs[NTOT];
__device__ float g_norms[NTOT];
__device__ int   g_gsums[256];

// ---------------- degree / normalization ----------------
__global__ void k_init_deg() {
    int i = blockIdx.x * 256 + threadIdx.x;
    if (i < NN) g_deg[i] = 1;                 // self-loop contributes 1
}

__global__ void k_hist(const int* __restrict__ dst) {
    int e = blockIdx.x * 256 + threadIdx.x;
    if (e < NE) atomicAdd(&g_deg[dst[e]], 1);
}

// exclusive scan of g_deg -> g_rowptr (2-level).  Also computes dinv.
__global__ void k_scan1() {
    __shared__ int sh[256];
    int t = threadIdx.x;
    int i = blockIdx.x * 256 + t;
    int v = (i < NN) ? g_deg[i] : 0;
    if (i < NN) g_dinv[i] = rsqrtf((float)v);  // deg >= 1 always (self loop)
    sh[t] = v; __syncthreads();
    #pragma unroll
    for (int o = 1; o < 256; o <<= 1) {
        int x = (t >= o) ? sh[t - o] : 0;
        __syncthreads();
        sh[t] += x;
        __syncthreads();
    }
    if (i < NN) g_rowptr[i] = sh[t] - v;       // block-local exclusive
    if (t == 255) g_gsums[blockIdx.x] = sh[255];
}

__global__ void k_scan2(int nb) {
    __shared__ int sh[256];
    int t = threadIdx.x;
    int v = (t < nb) ? g_gsums[t] : 0;
    sh[t] = v; __syncthreads();
    #pragma unroll
    for (int o = 1; o < 256; o <<= 1) {
        int x = (t >= o) ? sh[t - o] : 0;
        __syncthreads();
        sh[t] += x;
        __syncthreads();
    }
    g_gsums[t] = sh[t] - v;                    // exclusive
}

__global__ void k_scan3() {
    int i = blockIdx.x * 256 + threadIdx.x;
    if (i < NN) {
        int rp = g_rowptr[i] + g_gsums[i >> 8];
        g_rowptr[i] = rp;
        g_cursor[i] = rp;
    }
    if (i == 0) g_rowptr[NN] = NTOT;
}

// ---------------- bucket fill (CSR by dst) ----------------
__global__ void k_fill_edges(const int* __restrict__ src,
                             const int* __restrict__ dst) {
    int e = blockIdx.x * 256 + threadIdx.x;
    if (e < NE) {
        int s = src[e];
        int d = dst[e];
        int p = atomicAdd(&g_cursor[d], 1);
        g_srcs[p]  = s;
        g_norms[p] = g_dinv[s] * g_dinv[d];
    }
}

__global__ void k_fill_self() {
    int i = blockIdx.x * 256 + threadIdx.x;
    if (i < NN) {
        int p = atomicAdd(&g_cursor[i], 1);
        g_srcs[p] = i;
        float dv = g_dinv[i];
        g_norms[p] = dv * dv;
    }
}

// ---------------- SGEMM: C[N x BN] = A[N x 128] * W[128 x BN] ----------------
// BM=128 rows/block, BK=16, thread grid 16x16, each thread 8 x TN outputs.
template <int BN, int TN>
__global__ void __launch_bounds__(256)
k_gemm128(const float* __restrict__ A, const float* __restrict__ W,
          float* __restrict__ C, int N) {
    constexpr int BM = 128, BK = 16, K = 128;
    __shared__ float As[BM][BK];
    __shared__ float Ws[BK][BN];
    int tid = threadIdx.x;
    int ty  = tid >> 4;          // 0..15 : row group (8 rows each)
    int tx  = tid & 15;          // 0..15 : col group (TN cols each)
    int row0 = blockIdx.x * BM;

    float acc[8][TN];
    #pragma unroll
    for (int i = 0; i < 8; i++)
        #pragma unroll
        for (int j = 0; j < TN; j++) acc[i][j] = 0.f;

    for (int k0 = 0; k0 < K; k0 += BK) {
        // load A tile: 128x16 floats = 512 float4, 2 per thread
        #pragma unroll
        for (int l = 0; l < 2; l++) {
            int id = tid + l * 256;          // 0..511
            int r = id >> 2, c = id & 3;
            float4 v = make_float4(0.f, 0.f, 0.f, 0.f);
            if (row0 + r < N)
                v = *(const float4*)&A[(size_t)(row0 + r) * K + k0 + 4 * c];
            *(float4*)&As[r][4 * c] = v;
        }
        // load W tile: 16 x BN floats
        constexpr int WLOADS = (BK * BN) / (4 * 256);   // 2 (BN=128) or 1 (BN=64)
        #pragma unroll
        for (int l = 0; l < WLOADS; l++) {
            int id = tid + l * 256;
            int r = id / (BN / 4), c = id % (BN / 4);
            *(float4*)&Ws[r][4 * c] = *(const float4*)&W[(size_t)(k0 + r) * BN + 4 * c];
        }
        __syncthreads();

        #pragma unroll
        for (int kk = 0; kk < BK; kk++) {
            float a[8];
            #pragma unroll
            for (int i = 0; i < 8; i++) a[i] = As[ty * 8 + i][kk];
            float b[TN];
            #pragma unroll
            for (int j = 0; j < TN; j += 4) {
                float4 bv = *(const float4*)&Ws[kk][tx * TN + j];
                b[j] = bv.x; b[j + 1] = bv.y; b[j + 2] = bv.z; b[j + 3] = bv.w;
            }
            #pragma unroll
            for (int i = 0; i < 8; i++)
                #pragma unroll
                for (int j = 0; j < TN; j++)
                    acc[i][j] = fmaf(a[i], b[j], acc[i][j]);
        }
        __syncthreads();
    }

    #pragma unroll
    for (int i = 0; i < 8; i++) {
        int r = row0 + ty * 8 + i;
        if (r < N) {
            #pragma unroll
            for (int j = 0; j < TN; j += 4) {
                float4 v = make_float4(acc[i][j], acc[i][j + 1], acc[i][j + 2], acc[i][j + 3]);
                *(float4*)&C[(size_t)r * BN + tx * TN + j] = v;
            }
        }
    }
}

// ---------------- aggregation: out[d] = bias + sum_e norm[e]*m[src[e]] ----------------
template <int F, bool RELU>
__global__ void k_agg(const float* __restrict__ m, const float* __restrict__ bias,
                      float* __restrict__ out) {
    int node = blockIdx.x;
    int f = threadIdx.x;                // F threads
    int beg = g_rowptr[node];
    int end = g_rowptr[node + 1];
    float acc = 0.f;
    #pragma unroll 4
    for (int e = beg; e < end; e++) {
        int s = g_srcs[e];
        float w = g_norms[e];
        acc += w * __ldg(&m[(size_t)s * F + f]);
    }
    acc += bias[f];
    if (RELU) acc = fmaxf(acc, 0.f);
    out[(size_t)node * F + f] = acc;
}

// ---------------- log_softmax over 64 classes ----------------
__global__ void k_lsm(const float* __restrict__ logits, float* __restrict__ out) {
    int row = blockIdx.x * 4 + threadIdx.y;
    if (row >= NN) return;
    int t = threadIdx.x;
    const float* l = logits + (size_t)row * 64;
    float a = l[t], b = l[t + 32];
    float mx = fmaxf(a, b);
    #pragma unroll
    for (int o = 16; o; o >>= 1) mx = fmaxf(mx, __shfl_xor_sync(0xffffffffu, mx, o));
    float s = __expf(a - mx) + __expf(b - mx);
    #pragma unroll
    for (int o = 16; o; o >>= 1) s += __shfl_xor_sync(0xffffffffu, s, o);
    float lz = mx + __logf(s);
    float* o_ = out + (size_t)row * 64;
    o_[t] = a - lz;
    o_[t + 32] = b - lz;
}

// ---------------- launch ----------------
extern "C" void kernel_launch(void* const* d_in, const int* in_sizes, int n_in,
                              void* d_out, int out_size) {
    const float* x  = (const float*)d_in[0];
    const int*   ei = (const int*)d_in[1];     // int32! (JAX x64 disabled)
    const float* W1 = (const float*)d_in[2];
    const float* b1 = (const float*)d_in[3];
    const float* W2 = (const float*)d_in[4];
    const float* b2 = (const float*)d_in[5];
    const float* Wf = (const float*)d_in[6];
    const float* bf = (const float*)d_in[7];
    float* out = (float*)d_out;

    const int* src = ei;          // edge_index[0]
    const int* dst = ei + NE;     // edge_index[1]

    float *bufA, *bufB;
    cudaGetSymbolAddress((void**)&bufA, g_bufA);
    cudaGetSymbolAddress((void**)&bufB, g_bufB);

    const int nbN = (NN + 255) / 256;   // 196
    const int nbE = (NE + 255) / 256;

    // CSR-by-dst build (every call; deterministic work)
    k_init_deg<<<nbN, 256>>>();
    k_hist<<<nbE, 256>>>(dst);
    k_scan1<<<nbN, 256>>>();
    k_scan2<<<1, 256>>>(nbN);
    k_scan3<<<nbN, 256>>>();
    k_fill_edges<<<nbE, 256>>>(src, dst);
    k_fill_self<<<nbN, 256>>>();

    const int gb = (NN + 127) / 128;    // 391

    // layer 1: m = x @ W1 ; h = relu(agg(m) + b1)
    k_gemm128<128, 8><<<gb, 256>>>(x, W1, bufA, NN);
    k_agg<128, true><<<NN, 128>>>(bufA, b1, bufB);
    // layer 2
    k_gemm128<128, 8><<<gb, 256>>>(bufB, W2, bufA, NN);
    k_agg<128, true><<<NN, 128>>>(bufA, b2, bufB);
    // layer 3 (no relu)
    k_gemm128<64, 4><<<gb, 256>>>(bufB, Wf, bufA, NN);
    k_agg<64, false><<<NN, 64>>>(bufA, bf, bufB);
    // log_softmax
    k_lsm<<<(NN + 3) / 4, dim3(32, 4)>>>(bufB, out);
}